// round 11
// baseline (speedup 1.0000x reference)
#include <cuda_runtime.h>
#include <cuda_fp16.h>
#include <cstdint>
#include <cstddef>

#define DINLINE __device__ __forceinline__

// =====================================================================
// out[m][n] = sum_k x[m][k] * h[(n-k) & 127],   h = Re(ifft(b))
// Single-pass fp16 GEMM via mma.sync m16n8k16.
//  - Circulant: 16x16 B fragment depends only on d=(nbp-ks)&7 ->
//    8 fragments hoisted in regs, zero B traffic in mainloop.
//  - A fragments loaded DIRECTLY from global as float2 (no smem tile):
//    each quad reads one aligned 32B sector; 2 wf per LDG.64.
//  - Column-permuted F so epilogue is st.v4.f32 (coalesced).
// =====================================================================

static constexpr int D = 128;
static constexpr int TILE_M = 128;
static constexpr int RSF = 24;   // F tile row stride (halves), conflict-free
static constexpr int SMEM_TOTAL = 128 * RSF * 2;     // 6144 B (F only)

__device__ unsigned short g_h[128];   // fp16 bits of h

// ======================= Prep kernel: h = Re(ifft(b)) =======================

__global__ void __launch_bounds__(128) fourier_prep(const float* __restrict__ br,
                                                    const float* __restrict__ bi) {
    __shared__ float ct[128], st[128], sbr[128], sbi[128];
    int t = threadIdx.x;
    float ang = (float)t * (6.28318530717958647692f / 128.0f);
    float s, c;
    sincosf(ang, &s, &c);
    ct[t] = c; st[t] = s;
    sbr[t] = br[t]; sbi[t] = bi[t];
    __syncthreads();
    float acc = 0.0f;
    #pragma unroll 8
    for (int k = 0; k < 128; k++) {
        int idx = (k * t) & 127;             // exact integer angle reduction
        acc = fmaf(sbr[k], ct[idx], acc);
        acc = fmaf(-sbi[k], st[idx], acc);
    }
    acc *= (1.0f / 128.0f);
    g_h[t] = __half_as_ushort(__float2half_rn(acc));
}

// ======================= PTX wrappers =======================

DINLINE void mma16816(float* d, uint32_t a0, uint32_t a1, uint32_t a2, uint32_t a3,
                      uint32_t b0, uint32_t b1) {
    asm volatile(
        "mma.sync.aligned.m16n8k16.row.col.f32.f16.f16.f32 "
        "{%0,%1,%2,%3}, {%4,%5,%6,%7}, {%8,%9}, {%0,%1,%2,%3};"
        : "+f"(d[0]), "+f"(d[1]), "+f"(d[2]), "+f"(d[3])
        : "r"(a0), "r"(a1), "r"(a2), "r"(a3), "r"(b0), "r"(b1));
}

DINLINE void ldmatrix_x4(uint32_t& r0, uint32_t& r1, uint32_t& r2, uint32_t& r3,
                         uint32_t addr) {
    asm volatile("ldmatrix.sync.aligned.m8n8.x4.shared.b16 {%0,%1,%2,%3}, [%4];"
                 : "=r"(r0), "=r"(r1), "=r"(r2), "=r"(r3) : "r"(addr));
}

// column permutation within a 16-group: j -> output column offset
DINLINE int colmap(int j) {
    return (j < 8) ? (((j >> 1) << 2) | (j & 1))
                   : ((((j - 8) >> 1) << 2) | 2 | (j & 1));
}

// pack two fp32 -> one fp16x2 register (single F2FP.PACK_AB, round-to-nearest)
DINLINE uint32_t cvt_h2(float2 v) {
    uint32_t r;
    asm("cvt.rn.f16x2.f32 %0, %1, %2;" : "=r"(r) : "f"(v.y), "f"(v.x));
    return r;
}

// ======================= Main kernel =======================

__global__ void __launch_bounds__(256, 3)
fourier_main(const float* __restrict__ x, float* __restrict__ out) {
    extern __shared__ char smem[];
    __half* F = reinterpret_cast<__half*>(smem);

    const int tid  = threadIdx.x;
    const int warp = tid >> 5;
    const int lane = tid & 31;
    const int tile = blockIdx.x;

    const int r  = lane & 7;
    const int q  = lane >> 3;
    const int g  = lane >> 2;
    const int tg = lane & 3;

    // A-fragment global base pointers (row-contiguous float2 reads)
    const float* xr0 = x + (size_t)tile * (TILE_M * D)
                         + (size_t)(warp * 16 + g) * D + 2 * tg;
    const float* xr8 = xr0 + 8 * D;

    uint32_t a[8][4];

    // ---- batch 1: A fragments ks 0..3 (16 LDG.64 in flight) ----
    float2 t0[4][4];
    #pragma unroll
    for (int ks = 0; ks < 4; ks++) {
        t0[ks][0] = __ldcs(reinterpret_cast<const float2*>(xr0 + 16 * ks));
        t0[ks][1] = __ldcs(reinterpret_cast<const float2*>(xr8 + 16 * ks));
        t0[ks][2] = __ldcs(reinterpret_cast<const float2*>(xr0 + 16 * ks + 8));
        t0[ks][3] = __ldcs(reinterpret_cast<const float2*>(xr8 + 16 * ks + 8));
    }

    // ---- build F[n'][k] = h[(perm(n') - k) & 127], k in [0,16) ----
    #pragma unroll
    for (int u = 0; u < 4; u++) {
        int idx = u * 256 + tid;           // 128 rows x 8 u32 cols
        int n  = idx >> 3;
        int k  = (idx & 7) << 1;
        int pn = (n & ~15) + colmap(n & 15);
        uint32_t w = (uint32_t)g_h[(pn - k) & 127]
                   | ((uint32_t)g_h[(pn - k - 1) & 127] << 16);
        *reinterpret_cast<uint32_t*>(F + n * RSF + k) = w;
    }

    // ---- convert batch 1 ----
    #pragma unroll
    for (int ks = 0; ks < 4; ks++)
        #pragma unroll
        for (int j = 0; j < 4; j++)
            a[ks][j] = cvt_h2(t0[ks][j]);

    // ---- batch 2: A fragments ks 4..7 ----
    #pragma unroll
    for (int ks = 4; ks < 8; ks++) {
        t0[ks - 4][0] = __ldcs(reinterpret_cast<const float2*>(xr0 + 16 * ks));
        t0[ks - 4][1] = __ldcs(reinterpret_cast<const float2*>(xr8 + 16 * ks));
        t0[ks - 4][2] = __ldcs(reinterpret_cast<const float2*>(xr0 + 16 * ks + 8));
        t0[ks - 4][3] = __ldcs(reinterpret_cast<const float2*>(xr8 + 16 * ks + 8));
    }
    #pragma unroll
    for (int ks = 4; ks < 8; ks++)
        #pragma unroll
        for (int j = 0; j < 4; j++)
            a[ks][j] = cvt_h2(t0[ks - 4][j]);

    __syncthreads();   // F visible to all warps

    // ---- hoist 8 B diagonal fragments ----
    uint32_t b_addr = (uint32_t)__cvta_generic_to_shared(
        F + ((size_t)((q >> 1) * 8 + r)) * RSF + (q & 1) * 8);
    uint32_t b[8][4];
    #pragma unroll
    for (int d = 0; d < 8; d++)
        ldmatrix_x4(b[d][0], b[d][1], b[d][2], b[d][3],
                    b_addr + (uint32_t)(d * 16 * RSF * 2));

    // ---- mainloop: 128 MMAs + 16 coalesced STG.128, zero smem traffic ----
    float* op = out + (size_t)tile * (TILE_M * D) + (size_t)(warp * 16) * D;
    #pragma unroll
    for (int nbp = 0; nbp < 8; nbp++) {
        float acc0[4] = {0.f, 0.f, 0.f, 0.f};
        float acc1[4] = {0.f, 0.f, 0.f, 0.f};
        #pragma unroll
        for (int ks = 0; ks < 8; ks++) {
            const uint32_t* bd = b[(nbp - ks) & 7];
            mma16816(acc0, a[ks][0], a[ks][1], a[ks][2], a[ks][3], bd[0], bd[1]);
            mma16816(acc1, a[ks][0], a[ks][1], a[ks][2], a[ks][3], bd[2], bd[3]);
        }
        int col0 = nbp * 16 + 4 * tg;
        __stcs(reinterpret_cast<float4*>(op + (size_t)g * D + col0),
               make_float4(acc0[0], acc0[1], acc1[0], acc1[1]));
        __stcs(reinterpret_cast<float4*>(op + (size_t)(g + 8) * D + col0),
               make_float4(acc0[2], acc0[3], acc1[2], acc1[3]));
    }
}

// ======================= Harness entry =======================

extern "C" void kernel_launch(void* const* d_in, const int* in_sizes, int n_in,
                              void* d_out, int out_size) {
    const float* x  = (const float*)d_in[0];
    const float* br = (const float*)d_in[3];
    const float* bi = (const float*)d_in[4];
    float* out = (float*)d_out;

    int rows   = in_sizes[0] / D;       // 262144
    int ntiles = rows / TILE_M;         // 2048

    fourier_prep<<<1, 128>>>(br, bi);

    cudaFuncSetAttribute(fourier_main, cudaFuncAttributeMaxDynamicSharedMemorySize,
                         SMEM_TOTAL);
    fourier_main<<<ntiles, 256, SMEM_TOTAL>>>(x, out);
}

// round 13
// speedup vs baseline: 1.0718x; 1.0718x over previous
#include <cuda_runtime.h>
#include <cuda_fp16.h>
#include <cstdint>
#include <cstddef>

#define DINLINE __device__ __forceinline__

// =====================================================================
// out[m][n] = sum_k x[m][k] * h[(n-k) & 127],   h = Re(ifft(b))
// Single-pass fp16 GEMM via mma.sync m16n8k16.
//  - Persistent CTAs (grid 296 = 148 SM x 2): F tile + 8 circulant B
//    fragments built ONCE per CTA, amortized over ~7 tiles.
//  - A path (measured best, R7): coalesced LDG.128 -> fp16 STS -> ldmatrix.
//  - Cross-tile prefetch: next tile's LDGs issue under current tile's MMAs.
//  - Column-permuted F so epilogue is st.v4.f32 (coalesced).
// =====================================================================

static constexpr int D = 128;
static constexpr int TILE_M = 128;
static constexpr int RS  = 136;  // x tile row stride (halves), conflict-free
static constexpr int RSF = 24;   // F tile row stride (halves), conflict-free
static constexpr int F_OFF  = 0;
static constexpr int XH_OFF = 128 * RSF * 2;              // 6144
static constexpr int SMEM_TOTAL = XH_OFF + 128 * RS * 2;  // 40960
static constexpr int NCTAS = 296;                          // 148 SMs x 2

__device__ unsigned short g_h[128];   // fp16 bits of h

// ======================= Prep kernel: h = Re(ifft(b)) =======================

__global__ void __launch_bounds__(128) fourier_prep(const float* __restrict__ br,
                                                    const float* __restrict__ bi) {
    __shared__ float ct[128], st[128], sbr[128], sbi[128];
    int t = threadIdx.x;
    float ang = (float)t * (6.28318530717958647692f / 128.0f);
    float s, c;
    sincosf(ang, &s, &c);
    ct[t] = c; st[t] = s;
    sbr[t] = br[t]; sbi[t] = bi[t];
    __syncthreads();
    float acc = 0.0f;
    #pragma unroll 8
    for (int k = 0; k < 128; k++) {
        int idx = (k * t) & 127;             // exact integer angle reduction
        acc = fmaf(sbr[k], ct[idx], acc);
        acc = fmaf(-sbi[k], st[idx], acc);
    }
    acc *= (1.0f / 128.0f);
    g_h[t] = __half_as_ushort(__float2half_rn(acc));
}

// ======================= PTX wrappers =======================

DINLINE void mma16816(float* d, uint32_t a0, uint32_t a1, uint32_t a2, uint32_t a3,
                      uint32_t b0, uint32_t b1) {
    asm volatile(
        "mma.sync.aligned.m16n8k16.row.col.f32.f16.f16.f32 "
        "{%0,%1,%2,%3}, {%4,%5,%6,%7}, {%8,%9}, {%0,%1,%2,%3};"
        : "+f"(d[0]), "+f"(d[1]), "+f"(d[2]), "+f"(d[3])
        : "r"(a0), "r"(a1), "r"(a2), "r"(a3), "r"(b0), "r"(b1));
}

DINLINE void ldmatrix_x4(uint32_t& r0, uint32_t& r1, uint32_t& r2, uint32_t& r3,
                         uint32_t addr) {
    asm volatile("ldmatrix.sync.aligned.m8n8.x4.shared.b16 {%0,%1,%2,%3}, [%4];"
                 : "=r"(r0), "=r"(r1), "=r"(r2), "=r"(r3) : "r"(addr));
}

// column permutation within a 16-group: j -> output column offset
DINLINE int colmap(int j) {
    return (j < 8) ? (((j >> 1) << 2) | (j & 1))
                   : ((((j - 8) >> 1) << 2) | 2 | (j & 1));
}

// pack two fp32 -> one fp16x2 register (single F2FP, round-to-nearest)
DINLINE uint32_t cvt_h2(float a, float b) {
    uint32_t r;
    asm("cvt.rn.f16x2.f32 %0, %1, %2;" : "=r"(r) : "f"(b), "f"(a));
    return r;
}

// ======================= Main kernel =======================

__global__ void __launch_bounds__(256, 2)
fourier_main(const float* __restrict__ x, float* __restrict__ out, int ntiles) {
    extern __shared__ char smem[];
    __half* F  = reinterpret_cast<__half*>(smem + F_OFF);
    __half* XH = reinterpret_cast<__half*>(smem + XH_OFF);

    const int tid  = threadIdx.x;
    const int warp = tid >> 5;
    const int lane = tid & 31;

    const int r  = lane & 7;
    const int q  = lane >> 3;
    const int g  = lane >> 2;
    const int tg = lane & 3;

    int tile = blockIdx.x;

    // ---- prologue: issue tile0's 16 LDG.128 before any setup ----
    const float4* src = reinterpret_cast<const float4*>(x) + (size_t)tile * 4096;
    float4 v[8], w[8];
    #pragma unroll
    for (int it = 0; it < 8; it++) v[it] = __ldcs(src + it * 256 + tid);
    #pragma unroll
    for (int it = 0; it < 8; it++) w[it] = __ldcs(src + (it + 8) * 256 + tid);

    // ---- build F[n'][k] = h[(perm(n') - k) & 127], k in [0,16) — ONCE ----
    #pragma unroll
    for (int u = 0; u < 4; u++) {
        int idx = u * 256 + tid;           // 128 rows x 8 u32 cols
        int n  = idx >> 3;
        int k  = (idx & 7) << 1;
        int pn = (n & ~15) + colmap(n & 15);
        uint32_t fw = (uint32_t)g_h[(pn - k) & 127]
                    | ((uint32_t)g_h[(pn - k - 1) & 127] << 16);
        *reinterpret_cast<uint32_t*>(F + n * RSF + k) = fw;
    }
    __syncthreads();

    // ---- hoist 8 circulant B fragments — ONCE ----
    uint32_t b_addr = (uint32_t)__cvta_generic_to_shared(
        F + ((size_t)((q >> 1) * 8 + r)) * RSF + (q & 1) * 8);
    uint32_t b[8][4];
    #pragma unroll
    for (int d = 0; d < 8; d++)
        ldmatrix_x4(b[d][0], b[d][1], b[d][2], b[d][3],
                    b_addr + (uint32_t)(d * 16 * RSF * 2));

    uint32_t a_addr = (uint32_t)__cvta_generic_to_shared(
        XH + ((size_t)(warp * 16 + (q & 1) * 8 + r)) * RS + (q >> 1) * 8);

    // ---- persistent tile loop ----
    while (true) {
        // convert current tile to fp16, store to smem
        #pragma unroll
        for (int it = 0; it < 8; it++) {
            int i4 = it * 256 + tid;
            int row = i4 >> 5;
            int col = (i4 & 31) << 2;
            uint32_t* ph = reinterpret_cast<uint32_t*>(XH + row * RS + col);
            ph[0] = cvt_h2(v[it].x, v[it].y);
            ph[1] = cvt_h2(v[it].z, v[it].w);
        }
        #pragma unroll
        for (int it = 0; it < 8; it++) {
            int i4 = (it + 8) * 256 + tid;
            int row = i4 >> 5;
            int col = (i4 & 31) << 2;
            uint32_t* ph = reinterpret_cast<uint32_t*>(XH + row * RS + col);
            ph[0] = cvt_h2(w[it].x, w[it].y);
            ph[1] = cvt_h2(w[it].z, w[it].w);
        }
        __syncthreads();

        // A fragments for this tile
        uint32_t a[8][4];
        #pragma unroll
        for (int ks = 0; ks < 8; ks++)
            ldmatrix_x4(a[ks][0], a[ks][1], a[ks][2], a[ks][3], a_addr + ks * 32);
        __syncthreads();   // all warps done reading XH; safe to refill next iter

        int nt = tile + NCTAS;
        bool more = nt < ntiles;
        const float4* nsrc = reinterpret_cast<const float4*>(x) + (size_t)nt * 4096;

        // prefetch next tile (first half) under first MMA half
        if (more) {
            #pragma unroll
            for (int it = 0; it < 8; it++) v[it] = __ldcs(nsrc + it * 256 + tid);
        }

        float* op = out + (size_t)tile * (TILE_M * D) + (size_t)(warp * 16) * D;
        #pragma unroll
        for (int nbp = 0; nbp < 4; nbp++) {
            float acc0[4] = {0.f, 0.f, 0.f, 0.f};
            float acc1[4] = {0.f, 0.f, 0.f, 0.f};
            #pragma unroll
            for (int ks = 0; ks < 8; ks++) {
                const uint32_t* bd = b[(nbp - ks) & 7];
                mma16816(acc0, a[ks][0], a[ks][1], a[ks][2], a[ks][3], bd[0], bd[1]);
                mma16816(acc1, a[ks][0], a[ks][1], a[ks][2], a[ks][3], bd[2], bd[3]);
            }
            int col0 = nbp * 16 + 4 * tg;
            __stcs(reinterpret_cast<float4*>(op + (size_t)g * D + col0),
                   make_float4(acc0[0], acc0[1], acc1[0], acc1[1]));
            __stcs(reinterpret_cast<float4*>(op + (size_t)(g + 8) * D + col0),
                   make_float4(acc0[2], acc0[3], acc1[2], acc1[3]));
        }

        // prefetch next tile (second half) under second MMA half
        if (more) {
            #pragma unroll
            for (int it = 0; it < 8; it++) w[it] = __ldcs(nsrc + (it + 8) * 256 + tid);
        }

        #pragma unroll
        for (int nbp = 4; nbp < 8; nbp++) {
            float acc0[4] = {0.f, 0.f, 0.f, 0.f};
            float acc1[4] = {0.f, 0.f, 0.f, 0.f};
            #pragma unroll
            for (int ks = 0; ks < 8; ks++) {
                const uint32_t* bd = b[(nbp - ks) & 7];
                mma16816(acc0, a[ks][0], a[ks][1], a[ks][2], a[ks][3], bd[0], bd[1]);
                mma16816(acc1, a[ks][0], a[ks][1], a[ks][2], a[ks][3], bd[2], bd[3]);
            }
            int col0 = nbp * 16 + 4 * tg;
            __stcs(reinterpret_cast<float4*>(op + (size_t)g * D + col0),
                   make_float4(acc0[0], acc0[1], acc1[0], acc1[1]));
            __stcs(reinterpret_cast<float4*>(op + (size_t)(g + 8) * D + col0),
                   make_float4(acc0[2], acc0[3], acc1[2], acc1[3]));
        }

        if (!more) break;
        tile = nt;
    }
}

// ======================= Harness entry =======================

extern "C" void kernel_launch(void* const* d_in, const int* in_sizes, int n_in,
                              void* d_out, int out_size) {
    const float* x  = (const float*)d_in[0];
    const float* br = (const float*)d_in[3];
    const float* bi = (const float*)d_in[4];
    float* out = (float*)d_out;

    int rows   = in_sizes[0] / D;       // 262144
    int ntiles = rows / TILE_M;         // 2048

    fourier_prep<<<1, 128>>>(br, bi);

    cudaFuncSetAttribute(fourier_main, cudaFuncAttributeMaxDynamicSharedMemorySize,
                         SMEM_TOTAL);
    fourier_main<<<NCTAS, 256, SMEM_TOTAL>>>(x, out, ntiles);
}

// round 14
// speedup vs baseline: 1.1088x; 1.0345x over previous
#include <cuda_runtime.h>
#include <cuda_fp16.h>
#include <cstdint>
#include <cstddef>

#define DINLINE __device__ __forceinline__

// =====================================================================
// out[m][n] = sum_k x[m][k] * h[(n-k) & 127],   h = Re(ifft(b))
// Warp-autonomous fp16 GEMM via mma.sync m16n8k16:
//  - each warp owns an independent 16-row slab; NO syncs in main loop
//  - A fragments built from coalesced LDG.128 via warp shuffles
//    (zero smem traffic, zero STS/ldmatrix for A)
//  - circulant B: 8 fragments hoisted once per CTA (6KB smem F tile)
//  - column-permuted F so epilogue is st.v4.f32 (coalesced)
//  - persistent grid 444 = 148 SM x 3 CTAs
// =====================================================================

static constexpr int D = 128;
static constexpr int RSF = 24;                    // F row stride (halves)
static constexpr int SMEM_TOTAL = 128 * RSF * 2;  // 6144 B
static constexpr int NCTAS = 444;                 // 148 SMs x 3

__device__ unsigned short g_h[128];   // fp16 bits of h

// ======================= Prep kernel: h = Re(ifft(b)) =======================

__global__ void __launch_bounds__(128) fourier_prep(const float* __restrict__ br,
                                                    const float* __restrict__ bi) {
    __shared__ float ct[128], st[128], sbr[128], sbi[128];
    int t = threadIdx.x;
    float ang = (float)t * (6.28318530717958647692f / 128.0f);
    float s, c;
    sincosf(ang, &s, &c);
    ct[t] = c; st[t] = s;
    sbr[t] = br[t]; sbi[t] = bi[t];
    __syncthreads();
    float acc = 0.0f;
    #pragma unroll 8
    for (int k = 0; k < 128; k++) {
        int idx = (k * t) & 127;             // exact integer angle reduction
        acc = fmaf(sbr[k], ct[idx], acc);
        acc = fmaf(-sbi[k], st[idx], acc);
    }
    acc *= (1.0f / 128.0f);
    g_h[t] = __half_as_ushort(__float2half_rn(acc));
}

// ======================= PTX wrappers =======================

DINLINE void mma16816(float* d, uint32_t a0, uint32_t a1, uint32_t a2, uint32_t a3,
                      uint32_t b0, uint32_t b1) {
    asm volatile(
        "mma.sync.aligned.m16n8k16.row.col.f32.f16.f16.f32 "
        "{%0,%1,%2,%3}, {%4,%5,%6,%7}, {%8,%9}, {%0,%1,%2,%3};"
        : "+f"(d[0]), "+f"(d[1]), "+f"(d[2]), "+f"(d[3])
        : "r"(a0), "r"(a1), "r"(a2), "r"(a3), "r"(b0), "r"(b1));
}

DINLINE void ldmatrix_x4(uint32_t& r0, uint32_t& r1, uint32_t& r2, uint32_t& r3,
                         uint32_t addr) {
    asm volatile("ldmatrix.sync.aligned.m8n8.x4.shared.b16 {%0,%1,%2,%3}, [%4];"
                 : "=r"(r0), "=r"(r1), "=r"(r2), "=r"(r3) : "r"(addr));
}

// column permutation within a 16-group: j -> output column offset
DINLINE int colmap(int j) {
    return (j < 8) ? (((j >> 1) << 2) | (j & 1))
                   : ((((j - 8) >> 1) << 2) | 2 | (j & 1));
}

// pack two fp32 -> one fp16x2 register (single F2FP, round-to-nearest)
DINLINE uint32_t cvt_h2(float a, float b) {
    uint32_t r;
    asm("cvt.rn.f16x2.f32 %0, %1, %2;" : "=r"(r) : "f"(b), "f"(a));
    return r;
}

// ======================= Main kernel =======================

__global__ void __launch_bounds__(256, 3)
fourier_main(const float* __restrict__ x, float* __restrict__ out, int nslabs) {
    extern __shared__ char smem[];
    __half* F = reinterpret_cast<__half*>(smem);

    const int tid  = threadIdx.x;
    const int warp = tid >> 5;
    const int lane = tid & 31;

    const int r   = lane & 7;
    const int qq  = lane >> 3;         // ldmatrix quad
    const int g   = lane >> 2;
    const int tg  = lane & 3;

    const int m0 = (lane & ~3) | (tg >> 1);   // 4g + (tg>>1)
    const int m1 = m0 + 2;
    const bool oddtg = (tg & 1) != 0;

    int slab = blockIdx.x * 8 + warp;
    const int stride = NCTAS * 8;

    // ---- prologue: first slab's 16 LDG.128 in flight during F build ----
    float4 v[16];
    {
        const float4* src = reinterpret_cast<const float4*>(x) + (size_t)slab * 512;
        #pragma unroll
        for (int it = 0; it < 16; it++) {
            int u = it >> 1, h = it & 1;
            v[it] = __ldcs(src + (h * 8 + g) * 32 + u * 4 + tg);
        }
    }

    // ---- build F[n'][k] = h[(perm(n') - k) & 127], k in [0,16) — ONCE ----
    #pragma unroll
    for (int uu = 0; uu < 4; uu++) {
        int idx = uu * 256 + tid;          // 128 rows x 8 u32 cols
        int n  = idx >> 3;
        int k  = (idx & 7) << 1;
        int pn = (n & ~15) + colmap(n & 15);
        uint32_t fw = (uint32_t)g_h[(pn - k) & 127]
                    | ((uint32_t)g_h[(pn - k - 1) & 127] << 16);
        *reinterpret_cast<uint32_t*>(F + n * RSF + k) = fw;
    }
    __syncthreads();

    // ---- hoist 8 circulant B fragments — ONCE ----
    uint32_t b_addr = (uint32_t)__cvta_generic_to_shared(
        F + ((size_t)((qq >> 1) * 8 + r)) * RSF + (qq & 1) * 8);
    uint32_t b[8][4];
    #pragma unroll
    for (int d = 0; d < 8; d++)
        ldmatrix_x4(b[d][0], b[d][1], b[d][2], b[d][3],
                    b_addr + (uint32_t)(d * 16 * RSF * 2));

    // ---- pack first slab ----
    uint32_t qv[16][2];
    #pragma unroll
    for (int it = 0; it < 16; it++) {
        qv[it][0] = cvt_h2(v[it].x, v[it].y);
        qv[it][1] = cvt_h2(v[it].z, v[it].w);
    }

    // ---- warp-autonomous slab loop (no syncs) ----
    while (true) {
        // shuffles: qv -> A fragments
        uint32_t a[8][4];
        #pragma unroll
        for (int ks = 0; ks < 8; ks++) {
            uint32_t s00 = __shfl_sync(0xffffffffu, qv[2 * ks][0], m0);
            uint32_t s01 = __shfl_sync(0xffffffffu, qv[2 * ks][1], m0);
            a[ks][0] = oddtg ? s01 : s00;
            uint32_t s10 = __shfl_sync(0xffffffffu, qv[2 * ks + 1][0], m0);
            uint32_t s11 = __shfl_sync(0xffffffffu, qv[2 * ks + 1][1], m0);
            a[ks][1] = oddtg ? s11 : s10;
            uint32_t s20 = __shfl_sync(0xffffffffu, qv[2 * ks][0], m1);
            uint32_t s21 = __shfl_sync(0xffffffffu, qv[2 * ks][1], m1);
            a[ks][2] = oddtg ? s21 : s20;
            uint32_t s30 = __shfl_sync(0xffffffffu, qv[2 * ks + 1][0], m1);
            uint32_t s31 = __shfl_sync(0xffffffffu, qv[2 * ks + 1][1], m1);
            a[ks][3] = oddtg ? s31 : s30;
        }

        float* op = out + (size_t)slab * 16 * D;
        int next = slab + stride;
        bool more = next < nslabs;

        #pragma unroll
        for (int nbp = 0; nbp < 8; nbp++) {
            float acc0[4] = {0.f, 0.f, 0.f, 0.f};
            float acc1[4] = {0.f, 0.f, 0.f, 0.f};
            #pragma unroll
            for (int ks = 0; ks < 8; ks++) {
                const uint32_t* bd = b[(nbp - ks) & 7];
                mma16816(acc0, a[ks][0], a[ks][1], a[ks][2], a[ks][3], bd[0], bd[1]);
                mma16816(acc1, a[ks][0], a[ks][1], a[ks][2], a[ks][3], bd[2], bd[3]);
            }
            int col0 = nbp * 16 + 4 * tg;
            __stcs(reinterpret_cast<float4*>(op + (size_t)g * D + col0),
                   make_float4(acc0[0], acc0[1], acc1[0], acc1[1]));
            __stcs(reinterpret_cast<float4*>(op + (size_t)(g + 8) * D + col0),
                   make_float4(acc0[2], acc0[3], acc1[2], acc1[3]));
        }

        if (!more) break;
        slab = next;

        // load + pack next slab (ptxas pipelines the 16 LDGs)
        const float4* src = reinterpret_cast<const float4*>(x) + (size_t)slab * 512;
        #pragma unroll
        for (int it = 0; it < 16; it++) {
            int u = it >> 1, h = it & 1;
            float4 vv = __ldcs(src + (h * 8 + g) * 32 + u * 4 + tg);
            qv[it][0] = cvt_h2(vv.x, vv.y);
            qv[it][1] = cvt_h2(vv.z, vv.w);
        }
    }
}

// ======================= Harness entry =======================

extern "C" void kernel_launch(void* const* d_in, const int* in_sizes, int n_in,
                              void* d_out, int out_size) {
    const float* x  = (const float*)d_in[0];
    const float* br = (const float*)d_in[3];
    const float* bi = (const float*)d_in[4];
    float* out = (float*)d_out;

    int nslabs = in_sizes[0] / (16 * D);   // 16384 slabs of 16 rows

    fourier_prep<<<1, 128>>>(br, bi);

    cudaFuncSetAttribute(fourier_main, cudaFuncAttributeMaxDynamicSharedMemorySize,
                         SMEM_TOTAL);
    fourier_main<<<NCTAS, 256, SMEM_TOTAL>>>(x, out, nslabs);
}

// round 15
// speedup vs baseline: 1.2359x; 1.1146x over previous
#include <cuda_runtime.h>
#include <cuda_fp16.h>
#include <cstdint>
#include <cstddef>

#define DINLINE __device__ __forceinline__

// =====================================================================
// out[m][n] = sum_k x[m][k] * h[(n-k) & 127],   h = Re(ifft(b))
// Warp-autonomous fp16 GEMM via mma.sync m16n8k16:
//  - each warp owns independent 16-row slabs; NO syncs in main loop
//  - A fragments built from coalesced LDG.128 via warp shuffles
//  - software pipeline: next slab's LDGs issued in 4 batches INSIDE the
//    MMA loop, packed only after 2 nbp blocks of compute cover each batch
//  - circulant B: 8 fragments hoisted once per CTA (6KB smem F tile)
//  - column-permuted F so epilogue is st.v4.f32 (coalesced)
//  - persistent grid 296 = 148 SM x 2 CTAs (16 warps, 128 regs budget)
// =====================================================================

static constexpr int D = 128;
static constexpr int RSF = 24;                    // F row stride (halves)
static constexpr int SMEM_TOTAL = 128 * RSF * 2;  // 6144 B
static constexpr int NCTAS = 296;                 // 148 SMs x 2

__device__ unsigned short g_h[128];   // fp16 bits of h

// ======================= Prep kernel: h = Re(ifft(b)) =======================

__global__ void __launch_bounds__(128) fourier_prep(const float* __restrict__ br,
                                                    const float* __restrict__ bi) {
    __shared__ float ct[128], st[128], sbr[128], sbi[128];
    int t = threadIdx.x;
    float ang = (float)t * (6.28318530717958647692f / 128.0f);
    float s, c;
    sincosf(ang, &s, &c);
    ct[t] = c; st[t] = s;
    sbr[t] = br[t]; sbi[t] = bi[t];
    __syncthreads();
    float acc = 0.0f;
    #pragma unroll 8
    for (int k = 0; k < 128; k++) {
        int idx = (k * t) & 127;             // exact integer angle reduction
        acc = fmaf(sbr[k], ct[idx], acc);
        acc = fmaf(-sbi[k], st[idx], acc);
    }
    acc *= (1.0f / 128.0f);
    g_h[t] = __half_as_ushort(__float2half_rn(acc));
}

// ======================= PTX wrappers =======================

DINLINE void mma16816(float* d, uint32_t a0, uint32_t a1, uint32_t a2, uint32_t a3,
                      uint32_t b0, uint32_t b1) {
    asm volatile(
        "mma.sync.aligned.m16n8k16.row.col.f32.f16.f16.f32 "
        "{%0,%1,%2,%3}, {%4,%5,%6,%7}, {%8,%9}, {%0,%1,%2,%3};"
        : "+f"(d[0]), "+f"(d[1]), "+f"(d[2]), "+f"(d[3])
        : "r"(a0), "r"(a1), "r"(a2), "r"(a3), "r"(b0), "r"(b1));
}

DINLINE void ldmatrix_x4(uint32_t& r0, uint32_t& r1, uint32_t& r2, uint32_t& r3,
                         uint32_t addr) {
    asm volatile("ldmatrix.sync.aligned.m8n8.x4.shared.b16 {%0,%1,%2,%3}, [%4];"
                 : "=r"(r0), "=r"(r1), "=r"(r2), "=r"(r3) : "r"(addr));
}

// column permutation within a 16-group: j -> output column offset
DINLINE int colmap(int j) {
    return (j < 8) ? (((j >> 1) << 2) | (j & 1))
                   : ((((j - 8) >> 1) << 2) | 2 | (j & 1));
}

// pack two fp32 -> one fp16x2 register (single F2FP, round-to-nearest)
DINLINE uint32_t cvt_h2(float a, float b) {
    uint32_t r;
    asm("cvt.rn.f16x2.f32 %0, %1, %2;" : "=r"(r) : "f"(b), "f"(a));
    return r;
}

// ======================= Main kernel =======================

__global__ void __launch_bounds__(256, 2)
fourier_main(const float* __restrict__ x, float* __restrict__ out, int nslabs) {
    extern __shared__ char smem[];
    __half* F = reinterpret_cast<__half*>(smem);

    const int tid  = threadIdx.x;
    const int warp = tid >> 5;
    const int lane = tid & 31;

    const int r   = lane & 7;
    const int qq  = lane >> 3;         // ldmatrix quad
    const int g   = lane >> 2;
    const int tg  = lane & 3;

    const int m0 = (lane & ~3) | (tg >> 1);   // 4g + (tg>>1)
    const int m1 = m0 + 2;
    const bool oddtg = (tg & 1) != 0;

    int slab = blockIdx.x * 8 + warp;
    const int stride = NCTAS * 8;

    // per-lane load offset within a slab: iteration it = (u,h)
    //   addr = slab*512 + (h*8+g)*32 + u*4 + tg   (float4 units)
    const int loff = g * 32 + tg;

    // ---- prologue: first slab's 16 LDG.128 in flight during F build ----
    float4 v[16];
    {
        const float4* src = reinterpret_cast<const float4*>(x)
                          + (size_t)slab * 512 + loff;
        #pragma unroll
        for (int it = 0; it < 16; it++) {
            int u = it >> 1, h = it & 1;
            v[it] = __ldcs(src + h * 256 + u * 4);
        }
    }

    // ---- build F[n'][k] = h[(perm(n') - k) & 127], k in [0,16) — ONCE ----
    #pragma unroll
    for (int uu = 0; uu < 4; uu++) {
        int idx = uu * 256 + tid;          // 128 rows x 8 u32 cols
        int n  = idx >> 3;
        int k  = (idx & 7) << 1;
        int pn = (n & ~15) + colmap(n & 15);
        uint32_t fw = (uint32_t)g_h[(pn - k) & 127]
                    | ((uint32_t)g_h[(pn - k - 1) & 127] << 16);
        *reinterpret_cast<uint32_t*>(F + n * RSF + k) = fw;
    }
    __syncthreads();

    // ---- hoist 8 circulant B fragments — ONCE ----
    uint32_t b_addr = (uint32_t)__cvta_generic_to_shared(
        F + ((size_t)((qq >> 1) * 8 + r)) * RSF + (qq & 1) * 8);
    uint32_t b[8][4];
    #pragma unroll
    for (int d = 0; d < 8; d++)
        ldmatrix_x4(b[d][0], b[d][1], b[d][2], b[d][3],
                    b_addr + (uint32_t)(d * 16 * RSF * 2));

    // ---- pack first slab ----
    uint32_t qv[16][2];
    #pragma unroll
    for (int it = 0; it < 16; it++) {
        qv[it][0] = cvt_h2(v[it].x, v[it].y);
        qv[it][1] = cvt_h2(v[it].z, v[it].w);
    }

    // ---- warp-autonomous pipelined slab loop (no syncs) ----
    while (true) {
        // shuffles: qv -> A fragments (qv dead after this)
        uint32_t a[8][4];
        #pragma unroll
        for (int ks = 0; ks < 8; ks++) {
            uint32_t s00 = __shfl_sync(0xffffffffu, qv[2 * ks][0], m0);
            uint32_t s01 = __shfl_sync(0xffffffffu, qv[2 * ks][1], m0);
            a[ks][0] = oddtg ? s01 : s00;
            uint32_t s10 = __shfl_sync(0xffffffffu, qv[2 * ks + 1][0], m0);
            uint32_t s11 = __shfl_sync(0xffffffffu, qv[2 * ks + 1][1], m0);
            a[ks][1] = oddtg ? s11 : s10;
            uint32_t s20 = __shfl_sync(0xffffffffu, qv[2 * ks][0], m1);
            uint32_t s21 = __shfl_sync(0xffffffffu, qv[2 * ks][1], m1);
            a[ks][2] = oddtg ? s21 : s20;
            uint32_t s30 = __shfl_sync(0xffffffffu, qv[2 * ks + 1][0], m1);
            uint32_t s31 = __shfl_sync(0xffffffffu, qv[2 * ks + 1][1], m1);
            a[ks][3] = oddtg ? s31 : s30;
        }

        float* op = out + (size_t)slab * 16 * D;
        int next = slab + stride;
        bool more = next < nslabs;
        const float4* nsrc = reinterpret_cast<const float4*>(x)
                           + (size_t)next * 512 + loff;

        float4 nv[4];
        // batch 1 issue (its 0..3)
        if (more) {
            #pragma unroll
            for (int j = 0; j < 4; j++)
                nv[j] = __ldcs(nsrc + ((j & 1) ? 256 : 0) + (j >> 1) * 4);
        }

        #pragma unroll
        for (int half = 0; half < 4; half++) {
            // 2 nbp blocks of compute cover the batch just issued
            #pragma unroll
            for (int p = 0; p < 2; p++) {
                int nbp = half * 2 + p;
                float acc0[4] = {0.f, 0.f, 0.f, 0.f};
                float acc1[4] = {0.f, 0.f, 0.f, 0.f};
                #pragma unroll
                for (int ks = 0; ks < 8; ks++) {
                    const uint32_t* bd = b[(nbp - ks) & 7];
                    mma16816(acc0, a[ks][0], a[ks][1], a[ks][2], a[ks][3],
                             bd[0], bd[1]);
                    mma16816(acc1, a[ks][0], a[ks][1], a[ks][2], a[ks][3],
                             bd[2], bd[3]);
                }
                int col0 = nbp * 16 + 4 * tg;
                __stcs(reinterpret_cast<float4*>(op + (size_t)g * D + col0),
                       make_float4(acc0[0], acc0[1], acc1[0], acc1[1]));
                __stcs(reinterpret_cast<float4*>(op + (size_t)(g + 8) * D + col0),
                       make_float4(acc0[2], acc0[3], acc1[2], acc1[3]));
            }
            // pack the covered batch, issue the next one
            if (more) {
                #pragma unroll
                for (int j = 0; j < 4; j++) {
                    int it = half * 4 + j;            // (u = it>>1, h = it&1)
                    qv[it][0] = cvt_h2(nv[j].x, nv[j].y);
                    qv[it][1] = cvt_h2(nv[j].z, nv[j].w);
                }
                if (half < 3) {
                    #pragma unroll
                    for (int j = 0; j < 4; j++) {
                        int it = (half + 1) * 4 + j;
                        int u = it >> 1, h = it & 1;
                        nv[j] = __ldcs(nsrc + h * 256 + u * 4);
                    }
                }
            }
        }

        if (!more) break;
        slab = next;
    }
}

// ======================= Harness entry =======================

extern "C" void kernel_launch(void* const* d_in, const int* in_sizes, int n_in,
                              void* d_out, int out_size) {
    const float* x  = (const float*)d_in[0];
    const float* br = (const float*)d_in[3];
    const float* bi = (const float*)d_in[4];
    float* out = (float*)d_out;

    int nslabs = in_sizes[0] / (16 * D);   // 16384 slabs of 16 rows

    fourier_prep<<<1, 128>>>(br, bi);

    cudaFuncSetAttribute(fourier_main, cudaFuncAttributeMaxDynamicSharedMemorySize,
                         SMEM_TOTAL);
    fourier_main<<<NCTAS, 256, SMEM_TOTAL>>>(x, out, nslabs);
}